// round 6
// baseline (speedup 1.0000x reference)
#include <cuda_runtime.h>

// Depthwise conv_transpose2d(stride=4, k=7, bilinear) == separable x4 upsample.
// Input  x: [4, 256, 64, 64] fp32, Output: [4, 256, 259, 259] fp32.
//
// Compute (identical math to R5 rolling kernel):
//   out[o] = wA * in[cell-1] + (1-wA) * in[cell],  wA = 0.75 - 0.25*(o&3)
// One block per plane, thread ox rolls over 65 y-blocks keeping the
// horizontal blends of input rows a-1/a in registers (2 LDG per iter).
//
// Store path (new): the 4 output rows of a y-block are staged in smem,
// PRE-SHIFTED by each row's global alignment phase pad = (plane+3*oy)&3
// (constant over the loop: oy=4a+py -> pad depends only on plane,py).
// A copy phase then emits exactly 64 aligned float4 stores + 3 edge
// scalars per row: all STG.128, no split wavefronts, full 32B sectors.
// Double-buffered smem -> one __syncthreads per y-block.

namespace {
constexpr int H = 64, W = 64;
constexpr int OH = 259, OW = 259;
constexpr int PLANES = 4 * 256;     // 1024
constexpr int THREADS = 288;        // 9 warps
constexpr int SROW = 264;           // smem floats per row (pad + 259 <= 262)
}

__global__ void __launch_bounds__(THREADS)
bilinear_up4_smem_kernel(const float* __restrict__ x, float* __restrict__ out) {
    __shared__ float sm[2][4][SROW];

    int tid   = threadIdx.x;
    int plane = blockIdx.x;

    const float* __restrict__ xp = x + plane * (H * W);
    size_t planeBase = (size_t)plane * ((size_t)OH * OW);

    // ---- compute-phase role: one output column ox ----
    bool compute = tid < OW;
    int ox = tid;
    int b  = ox >> 2;
    int px = ox & 3;
    float wxA = 0.75f - 0.25f * (float)px;   // weight on col b-1 (0 at px==3)
    bool cAok = (b >= 1);
    bool cBok = (b < W);

    // per-row smem shift: pad(py) = (plane + 3*py) & 3
    int pad0 = (plane    ) & 3;
    int pad1 = (plane + 3) & 3;
    int pad2 = (plane + 6) & 3;
    int pad3 = (plane + 9) & 3;

    // ---- copy-phase role: row crow, unit cu (constant across loop) ----
    int crow = tid / 72;                     // 0..3
    int cu   = tid - crow * 72;              // 0..71
    int padr = (plane + 3 * crow) & 3;
    int hds  = (4 - padr) & 3;               // # head scalars for this row
    int j0   = padr ? 1 : 0;                 // first aligned chunk index

    // ---- rolling registers ----
    float hPrev = 0.0f, hCur = 0.0f;
    if (compute) {
        float v0 = cAok ? __ldg(xp + b - 1) : 0.0f;
        float v1 = cBok ? __ldg(xp + b)     : 0.0f;
        hCur = fmaf(wxA, v0 - v1, v1);
    }

#pragma unroll 1
    for (int a = 0; a <= 64; a++) {
        float (*s)[SROW] = sm[a & 1];

        // prefetch input row a+1 (OOB -> 0)
        float n0 = 0.0f, n1 = 0.0f;
        if (compute && a + 1 < H) {
            const float* row = xp + (a + 1) * W;
            n0 = cAok ? __ldg(row + b - 1) : 0.0f;
            n1 = cBok ? __ldg(row + b)     : 0.0f;
        }

        // compute 4 rows of y-block a into shifted smem slots
        if (compute) {
            float dh = hPrev - hCur;
            s[0][pad0 + ox] = fmaf(0.75f, dh, hCur);
            s[1][pad1 + ox] = fmaf(0.50f, dh, hCur);
            s[2][pad2 + ox] = fmaf(0.25f, dh, hCur);
            s[3][pad3 + ox] = hCur;
        }
        __syncthreads();

        // copy phase: aligned float4 chunks + edge scalars
        int oy = 4 * a + crow;
        if (oy < OH) {
            size_t S = planeBase + (size_t)oy * OW;     // S % 4 == padr
            float* dstBase = out + (S - padr);          // 16B-aligned origin
            if (cu < 64) {
                int j = j0 + cu;
                float4 v = *reinterpret_cast<const float4*>(&s[crow][4 * j]);
                *reinterpret_cast<float4*>(dstBase + 4 * j) = v;
            } else if (cu < 67) {
                int sc = cu - 64;                       // 0..2
                int go = (sc < hds) ? sc : 256 + sc;    // head else tail offset
                dstBase[padr + go] = s[crow][padr + go];
            }
        }

        hPrev = hCur;
        hCur  = fmaf(wxA, n0 - n1, n1);
    }
}

extern "C" void kernel_launch(void* const* d_in, const int* in_sizes, int n_in,
                              void* d_out, int out_size) {
    const float* x = (const float*)d_in[0];
    float* out = (float*)d_out;
    (void)in_sizes; (void)n_in; (void)out_size;

    bilinear_up4_smem_kernel<<<PLANES, THREADS>>>(x, out);
}